// round 10
// baseline (speedup 1.0000x reference)
#include <cuda_runtime.h>
#include <cstdint>

#define T_LEN 2048
#define B_SZ  256
#define IN_DIM 182
#define G3     192
#define KC     32
#define NCHUNK 6
#define M_TILE 128

typedef unsigned long long ull;

// scratch: IG[B*T,192] (~403MB)
__device__ float g_ig[(size_t)B_SZ * T_LEN * G3];

// ---------------- helpers ----------------
__device__ __forceinline__ uint32_t smem_u32(const void* p) {
    uint32_t a;
    asm("{ .reg .u64 t; cvta.to.shared.u64 t, %1; cvt.u32.u64 %0, t; }" : "=r"(a) : "l"(p));
    return a;
}
__device__ __forceinline__ void cp_async8(uint32_t dst, const void* src) {
    asm volatile("cp.async.ca.shared.global [%0], [%1], 8;" :: "r"(dst), "l"(src) : "memory");
}
#define CP_COMMIT() asm volatile("cp.async.commit_group;" ::: "memory")
#define CP_WAIT0()  asm volatile("cp.async.wait_group 0;" ::: "memory")

// m16n8k8 tf32 MMA
__device__ __forceinline__ void mma8(float* d, const uint32_t* a, uint32_t b0, uint32_t b1) {
    asm volatile("mma.sync.aligned.m16n8k8.row.col.f32.tf32.tf32.f32 "
                 "{%0,%1,%2,%3}, {%4,%5,%6,%7}, {%8,%9}, {%0,%1,%2,%3};"
                 : "+f"(d[0]), "+f"(d[1]), "+f"(d[2]), "+f"(d[3])
                 : "r"(a[0]), "r"(a[1]), "r"(a[2]), "r"(a[3]), "r"(b0), "r"(b1));
}

__device__ __forceinline__ void ffma2(ull& acc, ull a, ull b) {
    asm("fma.rn.f32x2 %0, %1, %2, %0;" : "+l"(acc) : "l"(a), "l"(b));
}
__device__ __forceinline__ void unpack2(float& lo, float& hi, ull v) {
    asm("mov.b64 {%0, %1}, %2;" : "=f"(lo), "=f"(hi) : "l"(v));
}
__device__ __forceinline__ float fsigmoid(float x) { return __fdividef(1.f, 1.f + __expf(-x)); }
__device__ __forceinline__ float ftanh(float x)    { return __fdividef(2.f, 1.f + __expf(-2.f * x)) - 1.f; }

// ---------------------------------------------------------------------------
// ig_mma: IG = X @ W^T via mma.sync tf32 (2-term hi/lo split of W), pipelined.
// B split computed IN-KERNEL from wih (register prefetch, convert+STS post-sync).
// Pair-interleaved B k-layout: lc -> koff = (lc>>3)*8 + ((lc&7)>>1) + 4*(lc&1),
// so each {b_k, b_{k+4}} fragment is one LDS.64.
// smem: A0[128][40] | A1[128][40] | Bh[192][40] | Bl[192][40] = 100KB (occ=1)
// ---------------------------------------------------------------------------
#define A_STRIDE 40
#define SMO_A0  0u
#define SMO_A1  20480u
#define SMO_BH  40960u
#define SMO_BL  71680u
#define SM_TOT  102400u

__global__ __launch_bounds__(256) void ig_mma(const float* __restrict__ X,
                                              const float* __restrict__ wih,
                                              const float* __restrict__ bias)
{
    extern __shared__ __align__(16) float smem[];
    float* Bh = smem + SMO_BH / 4;
    float* Bl = smem + SMO_BL / 4;
    const uint32_t sb = smem_u32(smem);

    const int tid  = threadIdx.x;
    const int wid  = tid >> 5;
    const int lane = tid & 31;
    const int mBase = blockIdx.x * M_TILE;

    const int wm = (wid & 3) * 32;
    const int wn = (wid >> 2) * 96;
    const int lr = lane >> 2;
    const int lc = lane & 3;

    float acc[2][12][4];
#pragma unroll
    for (int mf = 0; mf < 2; mf++)
#pragma unroll
        for (int nt = 0; nt < 12; nt++)
#pragma unroll
            for (int q = 0; q < 4; q++) acc[mf][nt][q] = 0.f;

    // A staging geometry
    const int row  = tid >> 1;
    const int half = tid & 1;
    const float* xrow = X + (size_t)(mBase + row) * IN_DIM;
    const uint32_t aRowOff = (uint32_t)(row * A_STRIDE + half * 16) * 4u;

    // B staging geometry: per-thread fixed (n0, lcB, koff); n = n0 + 8j
    const int n0  = tid >> 5;
    const int lcB = tid & 31;
    const int koff = ((lcB >> 3) << 3) + ((lcB & 7) >> 1) + 4 * (lcB & 1);

    auto stageA = [&](int c, uint32_t smoA) {
        const int kb = c * KC + half * 16;
        const uint32_t aBase = sb + smoA + aRowOff;
#pragma unroll
        for (int i = 0; i < 8; i++) {
            int kk = kb + 2 * i;
            if (kk + 1 < IN_DIM) cp_async8(aBase + (uint32_t)(8 * i), xrow + kk);
        }
        if (c == NCHUNK - 1 && half == 1) {
            float* ar = (float*)(smem + smoA / 4) + row * A_STRIDE;
            ar[22] = 1.0f;                         // bias column k=182
#pragma unroll
            for (int i = 23; i < 32; i++) ar[i] = 0.f;
        }
    };
    auto loadB = [&](int c, float* w) {            // 24 coalesced LDG
        const int k = c * KC + koff;
#pragma unroll
        for (int j = 0; j < 24; j++) {
            int n = n0 + 8 * j;
            w[j] = (k < IN_DIM) ? wih[n * IN_DIM + k]
                                : ((k == IN_DIM) ? bias[n] : 0.f);
        }
    };
    auto storeB = [&](const float* w) {            // split + STS (post-sync)
#pragma unroll
        for (int j = 0; j < 24; j++) {
            int off = (n0 + 8 * j) * A_STRIDE + lcB;
            float hi = __uint_as_float(__float_as_uint(w[j]) & 0xFFFFE000u);
            Bh[off] = hi;
            Bl[off] = w[j] - hi;
        }
    };

    // prologue
    float wreg[24];
    loadB(0, wreg);
    stageA(0, SMO_A0);
    CP_COMMIT();
    storeB(wreg);
    CP_WAIT0();
    __syncthreads();

    for (int c = 0; c < NCHUNK; c++) {
        if (c + 1 < NCHUNK) {
            loadB(c + 1, wreg);                    // LDG in flight over compute
            stageA(c + 1, ((c + 1) & 1) ? SMO_A1 : SMO_A0);
            CP_COMMIT();
        }
        const float* As = smem + ((c & 1) ? SMO_A1 : SMO_A0) / 4;

#pragma unroll
        for (int ks = 0; ks < 4; ks++) {
            uint32_t a[2][4];
#pragma unroll
            for (int mf = 0; mf < 2; mf++) {
                const float* ar  = As + (wm + mf * 16 + lr) * A_STRIDE + ks * 8 + lc;
                const float* ar8 = ar + 8 * A_STRIDE;
                a[mf][0] = __float_as_uint(ar[0]);
                a[mf][1] = __float_as_uint(ar8[0]);
                a[mf][2] = __float_as_uint(ar[4]);
                a[mf][3] = __float_as_uint(ar8[4]);
            }
#pragma unroll
            for (int nt = 0; nt < 12; nt++) {
                int boff = (wn + nt * 8 + lr) * A_STRIDE + ks * 8 + 2 * lc;
                uint2 bh = *(const uint2*)(Bh + boff);
                uint2 bl = *(const uint2*)(Bl + boff);
                mma8(acc[0][nt], a[0], bh.x, bh.y);
                mma8(acc[1][nt], a[1], bh.x, bh.y);
                mma8(acc[0][nt], a[0], bl.x, bl.y);
                mma8(acc[1][nt], a[1], bl.x, bl.y);
            }
        }
        __syncthreads();                           // done reading B(c)
        if (c + 1 < NCHUNK) {
            storeB(wreg);
            CP_WAIT0();                            // A(c+1) landed
            __syncthreads();
        }
    }

    // epilogue
#pragma unroll
    for (int mf = 0; mf < 2; mf++) {
        const int r0 = mBase + wm + mf * 16 + lr;
#pragma unroll
        for (int nt = 0; nt < 12; nt++) {
            const int col = wn + nt * 8 + 2 * lc;
            *(float2*)&g_ig[(size_t)r0 * G3 + col] =
                make_float2(acc[mf][nt][0], acc[mf][nt][1]);
            *(float2*)&g_ig[(size_t)(r0 + 8) * G3 + col] =
                make_float2(acc[mf][nt][2], acc[mf][nt][3]);
        }
    }
}

// ---------------------------------------------------------------------------
// GRU scan: 128 threads/CTA; hidden unit j = warp*16 + (lane&15), lanes l and
// l+16 split the k-range (32 each), combined by one shfl.bfly 16.
// Weights: 48 ull = 96 regs/thread (no spill). One barrier per step.
// ---------------------------------------------------------------------------
__global__ __launch_bounds__(128) void gru_scan(const float* __restrict__ whh,
                                                const float* __restrict__ bias_n,
                                                const float* __restrict__ wout,
                                                const float* __restrict__ out_bias,
                                                float* __restrict__ out)
{
    const int b = blockIdx.x;
    const int tid = threadIdx.x;
    const int w = tid >> 5;
    const int l = tid & 31;
    const int j  = (w << 4) + (l & 15);        // hidden unit 0..63
    const int kh = l >> 4;                     // k-half: 0 or 1
    const int kb = kh * 32;                    // k base
    const bool lead = (l < 16);

    __shared__ float sh_h[2][64];

    ull wr[16], wz[16], wn[16];
#pragma unroll
    for (int q = 0; q < 16; q++) {
        wr[q] = *(const ull*)&whh[(j)       * 64 + kb + 2 * q];
        wz[q] = *(const ull*)&whh[(64 + j)  * 64 + kb + 2 * q];
        wn[q] = *(const ull*)&whh[(128 + j) * 64 + kb + 2 * q];
    }
    const float bn = bias_n[j];

    float hreg = 0.f;
    if (lead) sh_h[0][j] = 0.f;

    const float* igp = g_ig + (size_t)b * T_LEN * G3;
    float pr[4], pz[4], pn[4];
    if (lead) {
#pragma unroll
        for (int u = 0; u < 4; u++) {
            const float* g = igp + (size_t)u * G3;
            pr[u] = g[j]; pz[u] = g[64 + j]; pn[u] = g[128 + j];
        }
    }
    __syncthreads();

    int p = 0;
    for (int t = 0; t < T_LEN; t += 4) {
#pragma unroll
        for (int u = 0; u < 4; u++) {
            // partial dots over this thread's 32-wide k-slice
            const float* hb = sh_h[p] + kb;
            ull ar = 0, az = 0, an = 0;
#pragma unroll
            for (int q = 0; q < 16; q += 2) {
                ulonglong2 h2 = *(const ulonglong2*)&hb[2 * q];   // pairs q, q+1
                ffma2(ar, wr[q], h2.x); ffma2(ar, wr[q + 1], h2.y);
                ffma2(az, wz[q], h2.x); ffma2(az, wz[q + 1], h2.y);
                ffma2(an, wn[q], h2.x); ffma2(an, wn[q + 1], h2.y);
            }
            float x0, x1;
            unpack2(x0, x1, ar); float fr = x0 + x1;
            unpack2(x0, x1, az); float fz = x0 + x1;
            unpack2(x0, x1, an); float fn = x0 + x1;
            fr += __shfl_xor_sync(0xFFFFFFFFu, fr, 16);
            fz += __shfl_xor_sync(0xFFFFFFFFu, fz, 16);
            fn += __shfl_xor_sync(0xFFFFFFFFu, fn, 16);

            if (lead) {
                const float igr = pr[u], igz = pz[u], ign = pn[u];
                const int tn = t + 4 + u;
                if (tn < T_LEN) {
                    const float* g = igp + (size_t)tn * G3;
                    pr[u] = g[j]; pz[u] = g[64 + j]; pn[u] = g[128 + j];
                }
                const float r = fsigmoid(igr + fr);
                const float z = fsigmoid(igz + fz);
                const float n = ftanh(ign + r * (fn + bn));
                hreg = n + z * (hreg - n);
                sh_h[1 - p][j] = hreg;
            }
            __syncthreads();
            p ^= 1;
        }
    }

    // readout (final h is in sh_h[p] after even number of flips)
    if (tid < 2) {
        float acc = 0.f;
        const float* hf = sh_h[p];
#pragma unroll 8
        for (int k = 0; k < 64; k++) acc += wout[tid * 64 + k] * hf[k];
        out[b * 2 + tid] = fsigmoid(acc + out_bias[tid]);
    }
}

// ---------------------------------------------------------------------------
extern "C" void kernel_launch(void* const* d_in, const int* in_sizes, int n_in,
                              void* d_out, int out_size)
{
    const float* x        = (const float*)d_in[0];
    const float* wih      = (const float*)d_in[1];
    const float* whh      = (const float*)d_in[2];
    const float* bias     = (const float*)d_in[3];
    const float* bias_n   = (const float*)d_in[4];
    const float* wout     = (const float*)d_in[5];
    const float* out_bias = (const float*)d_in[6];
    float* out = (float*)d_out;

    cudaFuncSetAttribute(ig_mma, cudaFuncAttributeMaxDynamicSharedMemorySize, SM_TOT);

    ig_mma<<<(B_SZ * T_LEN) / M_TILE, 256, SM_TOT>>>(x, wih, bias);
    gru_scan<<<B_SZ, 128>>>(whh, bias_n, wout, out_bias, out);
}

// round 11
// speedup vs baseline: 1.0054x; 1.0054x over previous
#include <cuda_runtime.h>
#include <cstdint>

#define T_LEN 2048
#define B_SZ  256
#define IN_DIM 182
#define G3     192
#define KC     32
#define NCHUNK 6
#define M_TILE 128

typedef unsigned long long ull;

// scratch: IG[B*T,192] (~403MB) + pair-interleaved split-B images [chunk][192][32]
__device__ float g_ig[(size_t)B_SZ * T_LEN * G3];
__device__ __align__(16) float g_bh[NCHUNK * G3 * KC];
__device__ __align__(16) float g_bl[NCHUNK * G3 * KC];

// ---------------- helpers ----------------
__device__ __forceinline__ uint32_t smem_u32(const void* p) {
    uint32_t a;
    asm("{ .reg .u64 t; cvta.to.shared.u64 t, %1; cvt.u32.u64 %0, t; }" : "=r"(a) : "l"(p));
    return a;
}
__device__ __forceinline__ void cp_async16(uint32_t dst, const void* src) {
    asm volatile("cp.async.cg.shared.global [%0], [%1], 16;" :: "r"(dst), "l"(src) : "memory");
}
__device__ __forceinline__ void cp_async8(uint32_t dst, const void* src) {
    asm volatile("cp.async.ca.shared.global [%0], [%1], 8;" :: "r"(dst), "l"(src) : "memory");
}
#define CP_COMMIT() asm volatile("cp.async.commit_group;" ::: "memory")
#define CP_WAIT0()  asm volatile("cp.async.wait_group 0;" ::: "memory")

// m16n8k8 tf32 MMA
__device__ __forceinline__ void mma8(float* d, const uint32_t* a, uint32_t b0, uint32_t b1) {
    asm volatile("mma.sync.aligned.m16n8k8.row.col.f32.tf32.tf32.f32 "
                 "{%0,%1,%2,%3}, {%4,%5,%6,%7}, {%8,%9}, {%0,%1,%2,%3};"
                 : "+f"(d[0]), "+f"(d[1]), "+f"(d[2]), "+f"(d[3])
                 : "r"(a[0]), "r"(a[1]), "r"(a[2]), "r"(a[3]), "r"(b0), "r"(b1));
}

__device__ __forceinline__ void ffma2(ull& acc, ull a, ull b) {
    asm("fma.rn.f32x2 %0, %1, %2, %0;" : "+l"(acc) : "l"(a), "l"(b));
}
__device__ __forceinline__ void unpack2(float& lo, float& hi, ull v) {
    asm("mov.b64 {%0, %1}, %2;" : "=f"(lo), "=f"(hi) : "l"(v));
}
__device__ __forceinline__ float fsigmoid(float x) { return __fdividef(1.f, 1.f + __expf(-x)); }
__device__ __forceinline__ float ftanh(float x)    { return __fdividef(2.f, 1.f + __expf(-2.f * x)) - 1.f; }

// ---------------------------------------------------------------------------
// prep_b: split W_ih (+bias as K-col 182) into tf32-exact hi + f32 lo.
// Pair-interleaved k inside each k8 group: lc -> k = c*32 + (lc>>3)*8 + ((lc&7)>>1) + 4*(lc&1)
// ---------------------------------------------------------------------------
__global__ void prep_b(const float* __restrict__ wih, const float* __restrict__ bias)
{
    int idx = blockIdx.x * 256 + threadIdx.x;      // 36864
    if (idx >= NCHUNK * G3 * KC) return;
    int c   = idx / (G3 * KC);
    int rem = idx % (G3 * KC);
    int n   = rem / KC;
    int lc  = rem % KC;
    int ks = lc >> 3, p = (lc & 7) >> 1, e = lc & 1;
    int k = c * KC + ks * 8 + p + 4 * e;
    float w = (k < IN_DIM) ? wih[n * IN_DIM + k] : ((k == IN_DIM) ? bias[n] : 0.f);
    float hi = __uint_as_float(__float_as_uint(w) & 0xFFFFE000u);
    g_bh[idx] = hi;
    g_bl[idx] = w - hi;
}

// ---------------------------------------------------------------------------
// ig_mma: IG = X @ W^T via mma.sync tf32 (2-term split), 2-stage A pipeline.
// (R8 version — verbatim; measured as part of the 1311 us config.)
// smem: A0[128][40] | A1[128][40] | Bh[192][40] | Bl[192][40]  -> 100KB
// ---------------------------------------------------------------------------
#define A_STRIDE 40
#define SMO_A0  0u
#define SMO_A1  20480u
#define SMO_BH  40960u
#define SMO_BL  71680u
#define SM_TOT  102400u

__global__ __launch_bounds__(256, 2) void ig_mma(const float* __restrict__ X)
{
    extern __shared__ __align__(16) float smem[];
    float* Bh = smem + SMO_BH / 4;
    float* Bl = smem + SMO_BL / 4;
    const uint32_t sb = smem_u32(smem);

    const int tid  = threadIdx.x;
    const int wid  = tid >> 5;
    const int lane = tid & 31;
    const int mBase = blockIdx.x * M_TILE;

    const int wm = (wid & 3) * 32;
    const int wn = (wid >> 2) * 96;
    const int lr = lane >> 2;
    const int lc = lane & 3;

    float acc[2][12][4];
#pragma unroll
    for (int mf = 0; mf < 2; mf++)
#pragma unroll
        for (int nt = 0; nt < 12; nt++)
#pragma unroll
            for (int q = 0; q < 4; q++) acc[mf][nt][q] = 0.f;

    const int row  = tid >> 1;
    const int half = tid & 1;
    const float* xrow = X + (size_t)(mBase + row) * IN_DIM;
    const uint32_t aRowOff = (uint32_t)(row * A_STRIDE + half * 16) * 4u;

    auto stageA = [&](int c, uint32_t smoA) {
        const int kb = c * KC + half * 16;
        const uint32_t aBase = sb + smoA + aRowOff;
#pragma unroll
        for (int i = 0; i < 8; i++) {
            int kk = kb + 2 * i;
            if (kk + 1 < IN_DIM) cp_async8(aBase + (uint32_t)(8 * i), xrow + kk);
        }
        if (c == NCHUNK - 1 && half == 1) {
            float* ar = (float*)(smem + smoA / 4) + row * A_STRIDE;
            ar[22] = 1.0f;                       // bias column k=182
#pragma unroll
            for (int i = 23; i < 32; i++) ar[i] = 0.f;
        }
    };
    auto stageB = [&](int c) {
        const float* srcH = g_bh + (size_t)c * G3 * KC;
        const float* srcL = g_bl + (size_t)c * G3 * KC;
#pragma unroll
        for (int j = 0; j < 6; j++) {
            int id = tid + j * 256;
            int n  = id >> 3;
            int q4 = (id & 7) * 4;
            uint32_t doff = (uint32_t)(n * A_STRIDE + q4) * 4u;
            cp_async16(sb + SMO_BH + doff, srcH + n * KC + q4);
            cp_async16(sb + SMO_BL + doff, srcL + n * KC + q4);
        }
    };

    // prologue
    stageA(0, SMO_A0);
    stageB(0);
    CP_COMMIT(); CP_WAIT0();
    __syncthreads();

    for (int c = 0; c < NCHUNK; c++) {
        if (c + 1 < NCHUNK) {
            stageA(c + 1, ((c + 1) & 1) ? SMO_A1 : SMO_A0);
            CP_COMMIT();
        }
        const float* As = smem + ((c & 1) ? SMO_A1 : SMO_A0) / 4;

#pragma unroll
        for (int ks = 0; ks < 4; ks++) {
            uint32_t a[2][4];
#pragma unroll
            for (int mf = 0; mf < 2; mf++) {
                const float* ar  = As + (wm + mf * 16 + lr) * A_STRIDE + ks * 8 + lc;
                const float* ar8 = ar + 8 * A_STRIDE;
                a[mf][0] = __float_as_uint(ar[0]);
                a[mf][1] = __float_as_uint(ar8[0]);
                a[mf][2] = __float_as_uint(ar[4]);
                a[mf][3] = __float_as_uint(ar8[4]);
            }
#pragma unroll
            for (int nt = 0; nt < 12; nt++) {
                int boff = (wn + nt * 8 + lr) * A_STRIDE + ks * 8 + 2 * lc;
                uint2 bh = *(const uint2*)(Bh + boff);
                uint2 bl = *(const uint2*)(Bl + boff);
                mma8(acc[0][nt], a[0], bh.x, bh.y);
                mma8(acc[1][nt], a[1], bh.x, bh.y);
                mma8(acc[0][nt], a[0], bl.x, bl.y);
                mma8(acc[1][nt], a[1], bl.x, bl.y);
            }
        }
        __syncthreads();                         // all warps done reading B(c)
        if (c + 1 < NCHUNK) {
            stageB(c + 1);
            CP_COMMIT(); CP_WAIT0();             // waits B(c+1) and A(c+1)
            __syncthreads();
        }
    }

    // epilogue
#pragma unroll
    for (int mf = 0; mf < 2; mf++) {
        const int r0 = mBase + wm + mf * 16 + lr;
#pragma unroll
        for (int nt = 0; nt < 12; nt++) {
            const int col = wn + nt * 8 + 2 * lc;
            *(float2*)&g_ig[(size_t)r0 * G3 + col] =
                make_float2(acc[mf][nt][0], acc[mf][nt][1]);
            *(float2*)&g_ig[(size_t)(r0 + 8) * G3 + col] =
                make_float2(acc[mf][nt][2], acc[mf][nt][3]);
        }
    }
}

// ---------------------------------------------------------------------------
// GRU scan: 128 threads/CTA; hidden unit j = warp*16 + (lane&15), lanes l and
// l+16 split the k-range (32 each), combined by one shfl.bfly 16.
// Weights: 48 ull = 96 regs/thread (no spill). One barrier per step.
// ---------------------------------------------------------------------------
__global__ __launch_bounds__(128) void gru_scan(const float* __restrict__ whh,
                                                const float* __restrict__ bias_n,
                                                const float* __restrict__ wout,
                                                const float* __restrict__ out_bias,
                                                float* __restrict__ out)
{
    const int b = blockIdx.x;
    const int tid = threadIdx.x;
    const int w = tid >> 5;
    const int l = tid & 31;
    const int j  = (w << 4) + (l & 15);        // hidden unit 0..63
    const int kb = (l >> 4) * 32;              // k base: 0 or 32
    const bool lead = (l < 16);

    __shared__ float sh_h[2][64];

    ull wr[16], wz[16], wn[16];
#pragma unroll
    for (int q = 0; q < 16; q++) {
        wr[q] = *(const ull*)&whh[(j)       * 64 + kb + 2 * q];
        wz[q] = *(const ull*)&whh[(64 + j)  * 64 + kb + 2 * q];
        wn[q] = *(const ull*)&whh[(128 + j) * 64 + kb + 2 * q];
    }
    const float bn = bias_n[j];

    float hreg = 0.f;
    if (lead) sh_h[0][j] = 0.f;

    const float* igp = g_ig + (size_t)b * T_LEN * G3;
    float pr[4], pz[4], pn[4];
    if (lead) {
#pragma unroll
        for (int u = 0; u < 4; u++) {
            const float* g = igp + (size_t)u * G3;
            pr[u] = g[j]; pz[u] = g[64 + j]; pn[u] = g[128 + j];
        }
    }
    __syncthreads();

    int p = 0;
    for (int t = 0; t < T_LEN; t += 4) {
#pragma unroll
        for (int u = 0; u < 4; u++) {
            // partial dots over this thread's 32-wide k-slice
            const float* hb = sh_h[p] + kb;
            ull ar = 0, az = 0, an = 0;
#pragma unroll
            for (int q = 0; q < 16; q += 2) {
                ulonglong2 h2 = *(const ulonglong2*)&hb[2 * q];   // pairs q, q+1
                ffma2(ar, wr[q], h2.x); ffma2(ar, wr[q + 1], h2.y);
                ffma2(az, wz[q], h2.x); ffma2(az, wz[q + 1], h2.y);
                ffma2(an, wn[q], h2.x); ffma2(an, wn[q + 1], h2.y);
            }
            float x0, x1;
            unpack2(x0, x1, ar); float fr = x0 + x1;
            unpack2(x0, x1, az); float fz = x0 + x1;
            unpack2(x0, x1, an); float fn = x0 + x1;
            fr += __shfl_xor_sync(0xFFFFFFFFu, fr, 16);
            fz += __shfl_xor_sync(0xFFFFFFFFu, fz, 16);
            fn += __shfl_xor_sync(0xFFFFFFFFu, fn, 16);

            if (lead) {
                const float igr = pr[u], igz = pz[u], ign = pn[u];
                const int tn = t + 4 + u;
                if (tn < T_LEN) {
                    const float* g = igp + (size_t)tn * G3;
                    pr[u] = g[j]; pz[u] = g[64 + j]; pn[u] = g[128 + j];
                }
                const float r = fsigmoid(igr + fr);
                const float z = fsigmoid(igz + fz);
                const float n = ftanh(ign + r * (fn + bn));
                hreg = n + z * (hreg - n);
                sh_h[1 - p][j] = hreg;
            }
            __syncthreads();
            p ^= 1;
        }
    }

    // readout (final h is in sh_h[p] after even number of flips)
    if (tid < 2) {
        float acc = 0.f;
        const float* hf = sh_h[p];
#pragma unroll 8
        for (int k = 0; k < 64; k++) acc += wout[tid * 64 + k] * hf[k];
        out[b * 2 + tid] = fsigmoid(acc + out_bias[tid]);
    }
}

// ---------------------------------------------------------------------------
extern "C" void kernel_launch(void* const* d_in, const int* in_sizes, int n_in,
                              void* d_out, int out_size)
{
    const float* x        = (const float*)d_in[0];
    const float* wih      = (const float*)d_in[1];
    const float* whh      = (const float*)d_in[2];
    const float* bias     = (const float*)d_in[3];
    const float* bias_n   = (const float*)d_in[4];
    const float* wout     = (const float*)d_in[5];
    const float* out_bias = (const float*)d_in[6];
    float* out = (float*)d_out;

    cudaFuncSetAttribute(ig_mma, cudaFuncAttributeMaxDynamicSharedMemorySize, SM_TOT);

    prep_b<<<(NCHUNK * G3 * KC + 255) / 256, 256>>>(wih, bias);
    ig_mma<<<(B_SZ * T_LEN) / M_TILE, 256, SM_TOT>>>(x);
    gru_scan<<<B_SZ, 128>>>(whh, bias_n, wout, out_bias, out);
}

// round 12
// speedup vs baseline: 1.5311x; 1.5229x over previous
#include <cuda_runtime.h>
#include <cstdint>

#define T_LEN 2048
#define B_SZ  256
#define IN_DIM 182
#define G3     192
#define KC     32
#define NCHUNK 6
#define M_TILE 128

typedef unsigned long long ull;

// scratch: IG[B*T,192] (~403MB)
__device__ float g_ig[(size_t)B_SZ * T_LEN * G3];

// ---------------- helpers ----------------
__device__ __forceinline__ uint32_t smem_u32(const void* p) {
    uint32_t a;
    asm("{ .reg .u64 t; cvta.to.shared.u64 t, %1; cvt.u32.u64 %0, t; }" : "=r"(a) : "l"(p));
    return a;
}
__device__ __forceinline__ void cp_async8(uint32_t dst, const void* src) {
    asm volatile("cp.async.ca.shared.global [%0], [%1], 8;" :: "r"(dst), "l"(src) : "memory");
}
#define CP_COMMIT() asm volatile("cp.async.commit_group;" ::: "memory")
#define CP_WAIT0()  asm volatile("cp.async.wait_group 0;" ::: "memory")

// m16n8k8 tf32 MMA
__device__ __forceinline__ void mma8(float* d, const uint32_t* a, uint32_t b0, uint32_t b1) {
    asm volatile("mma.sync.aligned.m16n8k8.row.col.f32.tf32.tf32.f32 "
                 "{%0,%1,%2,%3}, {%4,%5,%6,%7}, {%8,%9}, {%0,%1,%2,%3};"
                 : "+f"(d[0]), "+f"(d[1]), "+f"(d[2]), "+f"(d[3])
                 : "r"(a[0]), "r"(a[1]), "r"(a[2]), "r"(a[3]), "r"(b0), "r"(b1));
}

__device__ __forceinline__ void ffma2(ull& acc, ull a, ull b) {
    asm("fma.rn.f32x2 %0, %1, %2, %0;" : "+l"(acc) : "l"(a), "l"(b));
}
__device__ __forceinline__ void unpack2(float& lo, float& hi, ull v) {
    asm("mov.b64 {%0, %1}, %2;" : "=f"(lo), "=f"(hi) : "l"(v));
}
// fast activations via HW tanh (MUFU, 1 op instead of EX2+RCP chains)
__device__ __forceinline__ float tanh_fast(float x) {
    float y; asm("tanh.approx.f32 %0, %1;" : "=f"(y) : "f"(x)); return y;
}
__device__ __forceinline__ float fsigmoid(float x) { return fmaf(tanh_fast(0.5f * x), 0.5f, 0.5f); }
__device__ __forceinline__ float ftanh(float x)    { return tanh_fast(x); }

// ---------------------------------------------------------------------------
// ig_mma: IG = X @ W^T via mma.sync tf32 (2-term hi/lo split of W), pipelined.
// (R10 version verbatim — measured perf-neutral vs the prep_b variant.)
// B split computed IN-KERNEL from wih (register prefetch, convert+STS post-sync).
// Pair-interleaved B k-layout: lc -> koff = (lc>>3)*8 + ((lc&7)>>1) + 4*(lc&1).
// smem: A0[128][40] | A1[128][40] | Bh[192][40] | Bl[192][40] = 100KB
// ---------------------------------------------------------------------------
#define A_STRIDE 40
#define SMO_A0  0u
#define SMO_A1  20480u
#define SMO_BH  40960u
#define SMO_BL  71680u
#define SM_TOT  102400u

__global__ __launch_bounds__(256) void ig_mma(const float* __restrict__ X,
                                              const float* __restrict__ wih,
                                              const float* __restrict__ bias)
{
    extern __shared__ __align__(16) float smem[];
    float* Bh = smem + SMO_BH / 4;
    float* Bl = smem + SMO_BL / 4;
    const uint32_t sb = smem_u32(smem);

    const int tid  = threadIdx.x;
    const int wid  = tid >> 5;
    const int lane = tid & 31;
    const int mBase = blockIdx.x * M_TILE;

    const int wm = (wid & 3) * 32;
    const int wn = (wid >> 2) * 96;
    const int lr = lane >> 2;
    const int lc = lane & 3;

    float acc[2][12][4];
#pragma unroll
    for (int mf = 0; mf < 2; mf++)
#pragma unroll
        for (int nt = 0; nt < 12; nt++)
#pragma unroll
            for (int q = 0; q < 4; q++) acc[mf][nt][q] = 0.f;

    const int row  = tid >> 1;
    const int half = tid & 1;
    const float* xrow = X + (size_t)(mBase + row) * IN_DIM;
    const uint32_t aRowOff = (uint32_t)(row * A_STRIDE + half * 16) * 4u;

    const int n0  = tid >> 5;
    const int lcB = tid & 31;
    const int koff = ((lcB >> 3) << 3) + ((lcB & 7) >> 1) + 4 * (lcB & 1);

    auto stageA = [&](int c, uint32_t smoA) {
        const int kb = c * KC + half * 16;
        const uint32_t aBase = sb + smoA + aRowOff;
#pragma unroll
        for (int i = 0; i < 8; i++) {
            int kk = kb + 2 * i;
            if (kk + 1 < IN_DIM) cp_async8(aBase + (uint32_t)(8 * i), xrow + kk);
        }
        if (c == NCHUNK - 1 && half == 1) {
            float* ar = (float*)(smem + smoA / 4) + row * A_STRIDE;
            ar[22] = 1.0f;                         // bias column k=182
#pragma unroll
            for (int i = 23; i < 32; i++) ar[i] = 0.f;
        }
    };
    auto loadB = [&](int c, float* w) {            // 24 coalesced LDG
        const int k = c * KC + koff;
#pragma unroll
        for (int j = 0; j < 24; j++) {
            int n = n0 + 8 * j;
            w[j] = (k < IN_DIM) ? wih[n * IN_DIM + k]
                                : ((k == IN_DIM) ? bias[n] : 0.f);
        }
    };
    auto storeB = [&](const float* w) {            // split + STS (post-sync)
#pragma unroll
        for (int j = 0; j < 24; j++) {
            int off = (n0 + 8 * j) * A_STRIDE + lcB;
            float hi = __uint_as_float(__float_as_uint(w[j]) & 0xFFFFE000u);
            Bh[off] = hi;
            Bl[off] = w[j] - hi;
        }
    };

    // prologue
    float wreg[24];
    loadB(0, wreg);
    stageA(0, SMO_A0);
    CP_COMMIT();
    storeB(wreg);
    CP_WAIT0();
    __syncthreads();

    for (int c = 0; c < NCHUNK; c++) {
        if (c + 1 < NCHUNK) {
            loadB(c + 1, wreg);                    // LDG in flight over compute
            stageA(c + 1, ((c + 1) & 1) ? SMO_A1 : SMO_A0);
            CP_COMMIT();
        }
        const float* As = smem + ((c & 1) ? SMO_A1 : SMO_A0) / 4;

#pragma unroll
        for (int ks = 0; ks < 4; ks++) {
            uint32_t a[2][4];
#pragma unroll
            for (int mf = 0; mf < 2; mf++) {
                const float* ar  = As + (wm + mf * 16 + lr) * A_STRIDE + ks * 8 + lc;
                const float* ar8 = ar + 8 * A_STRIDE;
                a[mf][0] = __float_as_uint(ar[0]);
                a[mf][1] = __float_as_uint(ar8[0]);
                a[mf][2] = __float_as_uint(ar[4]);
                a[mf][3] = __float_as_uint(ar8[4]);
            }
#pragma unroll
            for (int nt = 0; nt < 12; nt++) {
                int boff = (wn + nt * 8 + lr) * A_STRIDE + ks * 8 + 2 * lc;
                uint2 bh = *(const uint2*)(Bh + boff);
                uint2 bl = *(const uint2*)(Bl + boff);
                mma8(acc[0][nt], a[0], bh.x, bh.y);
                mma8(acc[1][nt], a[1], bh.x, bh.y);
                mma8(acc[0][nt], a[0], bl.x, bl.y);
                mma8(acc[1][nt], a[1], bl.x, bl.y);
            }
        }
        __syncthreads();                           // done reading B(c)
        if (c + 1 < NCHUNK) {
            storeB(wreg);
            CP_WAIT0();                            // A(c+1) landed
            __syncthreads();
        }
    }

    // epilogue
#pragma unroll
    for (int mf = 0; mf < 2; mf++) {
        const int r0 = mBase + wm + mf * 16 + lr;
#pragma unroll
        for (int nt = 0; nt < 12; nt++) {
            const int col = wn + nt * 8 + 2 * lc;
            *(float2*)&g_ig[(size_t)r0 * G3 + col] =
                make_float2(acc[mf][nt][0], acc[mf][nt][1]);
            *(float2*)&g_ig[(size_t)(r0 + 8) * G3 + col] =
                make_float2(acc[mf][nt][2], acc[mf][nt][3]);
        }
    }
}

// ---------------------------------------------------------------------------
// GRU scan: R8's 64-thread version (fastest measured), with tanh.approx
// activations. Thread j owns gate rows j / 64+j / 128+j entirely (weights in
// registers). h double-buffered in smem -> ONE barrier per step.
// ---------------------------------------------------------------------------
__global__ __launch_bounds__(64) void gru_scan(const float* __restrict__ whh,
                                               const float* __restrict__ bias_n,
                                               const float* __restrict__ wout,
                                               const float* __restrict__ out_bias,
                                               float* __restrict__ out)
{
    const int b = blockIdx.x;
    const int j = threadIdx.x;                 // 0..63

    __shared__ float sh_h[2][64];

    ull wr[32], wz[32], wn[32];
#pragma unroll
    for (int q = 0; q < 32; q++) {
        wr[q] = *(const ull*)&whh[(j)        * 64 + 2 * q];
        wz[q] = *(const ull*)&whh[(64 + j)   * 64 + 2 * q];
        wn[q] = *(const ull*)&whh[(128 + j)  * 64 + 2 * q];
    }
    const float bn = bias_n[j];

    float hreg = 0.f;
    sh_h[0][j] = 0.f;

    const float* igp = g_ig + (size_t)b * T_LEN * G3;
    float pr[4], pz[4], pn[4];
#pragma unroll
    for (int u = 0; u < 4; u++) {
        const float* g = igp + (size_t)u * G3;
        pr[u] = g[j]; pz[u] = g[64 + j]; pn[u] = g[128 + j];
    }
    __syncthreads();

    int p = 0;
    for (int t = 0; t < T_LEN; t += 4) {
#pragma unroll
        for (int u = 0; u < 4; u++) {
            const float igr = pr[u], igz = pz[u], ign = pn[u];
            const int tn = t + 4 + u;
            if (tn < T_LEN) {
                const float* g = igp + (size_t)tn * G3;
                pr[u] = g[j]; pz[u] = g[64 + j]; pn[u] = g[128 + j];
            }

            // three 64-dot products against shared h
            ull ar0 = 0, ar1 = 0, az0 = 0, az1 = 0, an0 = 0, an1 = 0;
            const float* hb = sh_h[p];
#pragma unroll
            for (int q = 0; q < 32; q += 2) {
                ulonglong2 h2 = *(const ulonglong2*)&hb[2 * q];   // pairs q, q+1
                ffma2(ar0, wr[q], h2.x); ffma2(ar1, wr[q + 1], h2.y);
                ffma2(az0, wz[q], h2.x); ffma2(az1, wz[q + 1], h2.y);
                ffma2(an0, wn[q], h2.x); ffma2(an1, wn[q + 1], h2.y);
            }
            float x0, x1, y0, y1;
            unpack2(x0, x1, ar0); unpack2(y0, y1, ar1);
            const float hgr = (x0 + x1) + (y0 + y1);
            unpack2(x0, x1, az0); unpack2(y0, y1, az1);
            const float hgz = (x0 + x1) + (y0 + y1);
            unpack2(x0, x1, an0); unpack2(y0, y1, an1);
            const float hgn = (x0 + x1) + (y0 + y1);

            const float r = fsigmoid(igr + hgr);
            const float z = fsigmoid(igz + hgz);
            const float n = ftanh(ign + r * (hgn + bn));
            hreg = n + z * (hreg - n);

            sh_h[1 - p][j] = hreg;
            __syncthreads();
            p ^= 1;
        }
    }

    // readout
    sh_h[0][j] = hreg;
    __syncthreads();
    if (j < 2) {
        float acc = 0.f;
#pragma unroll 8
        for (int k = 0; k < 64; k++) acc += wout[j * 64 + k] * sh_h[0][k];
        out[b * 2 + j] = fsigmoid(acc + out_bias[j]);
    }
}

// ---------------------------------------------------------------------------
extern "C" void kernel_launch(void* const* d_in, const int* in_sizes, int n_in,
                              void* d_out, int out_size)
{
    const float* x        = (const float*)d_in[0];
    const float* wih      = (const float*)d_in[1];
    const float* whh      = (const float*)d_in[2];
    const float* bias     = (const float*)d_in[3];
    const float* bias_n   = (const float*)d_in[4];
    const float* wout     = (const float*)d_in[5];
    const float* out_bias = (const float*)d_in[6];
    float* out = (float*)d_out;

    cudaFuncSetAttribute(ig_mma, cudaFuncAttributeMaxDynamicSharedMemorySize, SM_TOT);

    ig_mma<<<(B_SZ * T_LEN) / M_TILE, 256, SM_TOT>>>(x, wih, bias);
    gru_scan<<<B_SZ, 64>>>(whh, bias_n, wout, out_bias, out);
}

// round 13
// speedup vs baseline: 1.7533x; 1.1451x over previous
#include <cuda_runtime.h>
#include <cstdint>

#define T_LEN 2048
#define B_SZ  256
#define IN_DIM 182
#define G3     192
#define KC     32
#define NCHUNK 6
#define M_TILE 128

typedef unsigned long long ull;

// scratch: IG[B*T,192] (~403MB) + pair-interleaved split-B images [chunk][192][32]
__device__ float g_ig[(size_t)B_SZ * T_LEN * G3];
__device__ __align__(16) float g_bh[NCHUNK * G3 * KC];
__device__ __align__(16) float g_bl[NCHUNK * G3 * KC];

// ---------------- helpers ----------------
__device__ __forceinline__ uint32_t smem_u32(const void* p) {
    uint32_t a;
    asm("{ .reg .u64 t; cvta.to.shared.u64 t, %1; cvt.u32.u64 %0, t; }" : "=r"(a) : "l"(p));
    return a;
}
__device__ __forceinline__ void cp_async16(uint32_t dst, const void* src) {
    asm volatile("cp.async.cg.shared.global [%0], [%1], 16;" :: "r"(dst), "l"(src) : "memory");
}
__device__ __forceinline__ void cp_async8(uint32_t dst, const void* src) {
    asm volatile("cp.async.ca.shared.global [%0], [%1], 8;" :: "r"(dst), "l"(src) : "memory");
}
#define CP_COMMIT() asm volatile("cp.async.commit_group;" ::: "memory")
#define CP_WAIT0()  asm volatile("cp.async.wait_group 0;" ::: "memory")

// m16n8k8 tf32 MMA
__device__ __forceinline__ void mma8(float* d, const uint32_t* a, uint32_t b0, uint32_t b1) {
    asm volatile("mma.sync.aligned.m16n8k8.row.col.f32.tf32.tf32.f32 "
                 "{%0,%1,%2,%3}, {%4,%5,%6,%7}, {%8,%9}, {%0,%1,%2,%3};"
                 : "+f"(d[0]), "+f"(d[1]), "+f"(d[2]), "+f"(d[3])
                 : "r"(a[0]), "r"(a[1]), "r"(a[2]), "r"(a[3]), "r"(b0), "r"(b1));
}

__device__ __forceinline__ void ffma2(ull& acc, ull a, ull b) {
    asm("fma.rn.f32x2 %0, %1, %2, %0;" : "+l"(acc) : "l"(a), "l"(b));
}
__device__ __forceinline__ void unpack2(float& lo, float& hi, ull v) {
    asm("mov.b64 {%0, %1}, %2;" : "=f"(lo), "=f"(hi) : "l"(v));
}
// fast activations via HW tanh
__device__ __forceinline__ float tanh_fast(float x) {
    float y; asm("tanh.approx.f32 %0, %1;" : "=f"(y) : "f"(x)); return y;
}
__device__ __forceinline__ float fsigmoid(float x) { return fmaf(tanh_fast(0.5f * x), 0.5f, 0.5f); }
__device__ __forceinline__ float ftanh(float x)    { return tanh_fast(x); }

// ---------------------------------------------------------------------------
// prep_b: split W_ih (+bias as K-col 182) into tf32-exact hi + f32 lo.
// Pair-interleaved k inside each k8 group.
// ---------------------------------------------------------------------------
__global__ void prep_b(const float* __restrict__ wih, const float* __restrict__ bias)
{
    int idx = blockIdx.x * 256 + threadIdx.x;      // 36864
    if (idx >= NCHUNK * G3 * KC) return;
    int c   = idx / (G3 * KC);
    int rem = idx % (G3 * KC);
    int n   = rem / KC;
    int lc  = rem % KC;
    int ks = lc >> 3, p = (lc & 7) >> 1, e = lc & 1;
    int k = c * KC + ks * 8 + p + 4 * e;
    float w = (k < IN_DIM) ? wih[n * IN_DIM + k] : ((k == IN_DIM) ? bias[n] : 0.f);
    float hi = __uint_as_float(__float_as_uint(w) & 0xFFFFE000u);
    g_bh[idx] = hi;
    g_bl[idx] = w - hi;
}

// ---------------------------------------------------------------------------
// ig_mma: R7 version VERBATIM (measured ~490us) — single A buffer, occ 2.
// smem: A[128][40] | Bh[192][40] | Bl[192][40] = 80KB
// ---------------------------------------------------------------------------
#define A_STRIDE 40
#define SMO_A   0u
#define SMO_BH  20480u
#define SMO_BL  51200u
#define SM_TOT  81920u

__global__ __launch_bounds__(256, 2) void ig_mma(const float* __restrict__ X)
{
    extern __shared__ __align__(16) float smem[];
    float* As = smem;                        // [128][40]
    float* Bh = smem + SMO_BH / 4;           // [192][40]
    float* Bl = smem + SMO_BL / 4;
    const uint32_t sb = smem_u32(smem);

    const int tid  = threadIdx.x;
    const int wid  = tid >> 5;
    const int lane = tid & 31;
    const int mBase = blockIdx.x * M_TILE;

    const int wm = (wid & 3) * 32;
    const int wn = (wid >> 2) * 96;
    const int lr = lane >> 2;
    const int lc = lane & 3;

    float acc[2][12][4];
#pragma unroll
    for (int mf = 0; mf < 2; mf++)
#pragma unroll
        for (int nt = 0; nt < 12; nt++)
#pragma unroll
            for (int q = 0; q < 4; q++) acc[mf][nt][q] = 0.f;

    const int row  = tid >> 1;
    const int half = tid & 1;
    const float* xrow = X + (size_t)(mBase + row) * IN_DIM;

    for (int c = 0; c < NCHUNK; c++) {
        // ---- stage B (hi+lo): 6 x 16B per term per thread ----
        const float* srcH = g_bh + (size_t)c * G3 * KC;
        const float* srcL = g_bl + (size_t)c * G3 * KC;
#pragma unroll
        for (int j = 0; j < 6; j++) {
            int id = tid + j * 256;
            int n  = id >> 3;
            int q4 = (id & 7) * 4;
            uint32_t doff = (uint32_t)(n * A_STRIDE + q4) * 4u;
            cp_async16(sb + SMO_BH + doff, srcH + n * KC + q4);
            cp_async16(sb + SMO_BL + doff, srcL + n * KC + q4);
        }
        // ---- stage A: 8 x 8B per thread (X rows are 8B-aligned) ----
        const int kb = c * KC + half * 16;
        const uint32_t aBase = sb + SMO_A + (uint32_t)(row * A_STRIDE + half * 16) * 4u;
#pragma unroll
        for (int i = 0; i < 8; i++) {
            int kk = kb + 2 * i;
            if (kk + 1 < IN_DIM)
                cp_async8(aBase + (uint32_t)(8 * i), xrow + kk);
        }
        if (c == NCHUNK - 1 && half == 1) {
            float* ar = As + row * A_STRIDE;
            ar[22] = 1.0f;
#pragma unroll
            for (int i = 23; i < 32; i++) ar[i] = 0.f;
        }
        CP_COMMIT();
        CP_WAIT0();
        __syncthreads();

        // ---- compute: 4 k8-steps ----
#pragma unroll
        for (int ks = 0; ks < 4; ks++) {
            uint32_t a[2][4];
#pragma unroll
            for (int mf = 0; mf < 2; mf++) {
                const float* ar  = As + (wm + mf * 16 + lr) * A_STRIDE + ks * 8 + lc;
                const float* ar8 = ar + 8 * A_STRIDE;
                a[mf][0] = __float_as_uint(ar[0]);
                a[mf][1] = __float_as_uint(ar8[0]);
                a[mf][2] = __float_as_uint(ar[4]);
                a[mf][3] = __float_as_uint(ar8[4]);
            }
#pragma unroll
            for (int nt = 0; nt < 12; nt++) {
                int boff = (wn + nt * 8 + lr) * A_STRIDE + ks * 8 + 2 * lc;
                uint2 bh = *(const uint2*)(Bh + boff);
                uint2 bl = *(const uint2*)(Bl + boff);
                mma8(acc[0][nt], a[0], bh.x, bh.y);
                mma8(acc[1][nt], a[1], bh.x, bh.y);
                mma8(acc[0][nt], a[0], bl.x, bl.y);
                mma8(acc[1][nt], a[1], bl.x, bl.y);
            }
        }
        __syncthreads();
    }

    // ---- epilogue ----
#pragma unroll
    for (int mf = 0; mf < 2; mf++) {
        const int r0 = mBase + wm + mf * 16 + lr;
#pragma unroll
        for (int nt = 0; nt < 12; nt++) {
            const int col = wn + nt * 8 + 2 * lc;
            *(float2*)&g_ig[(size_t)r0 * G3 + col] =
                make_float2(acc[mf][nt][0], acc[mf][nt][1]);
            *(float2*)&g_ig[(size_t)(r0 + 8) * G3 + col] =
                make_float2(acc[mf][nt][2], acc[mf][nt][3]);
        }
    }
}

// ---------------------------------------------------------------------------
// GRU scan: R12 version VERBATIM (measured 580us) — 64 threads, weights in
// registers, tanh.approx activations, 1 barrier/step, 4-deep ig prefetch.
// ---------------------------------------------------------------------------
__global__ __launch_bounds__(64) void gru_scan(const float* __restrict__ whh,
                                               const float* __restrict__ bias_n,
                                               const float* __restrict__ wout,
                                               const float* __restrict__ out_bias,
                                               float* __restrict__ out)
{
    const int b = blockIdx.x;
    const int j = threadIdx.x;                 // 0..63

    __shared__ float sh_h[2][64];

    ull wr[32], wz[32], wn[32];
#pragma unroll
    for (int q = 0; q < 32; q++) {
        wr[q] = *(const ull*)&whh[(j)        * 64 + 2 * q];
        wz[q] = *(const ull*)&whh[(64 + j)   * 64 + 2 * q];
        wn[q] = *(const ull*)&whh[(128 + j)  * 64 + 2 * q];
    }
    const float bn = bias_n[j];

    float hreg = 0.f;
    sh_h[0][j] = 0.f;

    const float* igp = g_ig + (size_t)b * T_LEN * G3;
    float pr[4], pz[4], pn[4];
#pragma unroll
    for (int u = 0; u < 4; u++) {
        const float* g = igp + (size_t)u * G3;
        pr[u] = g[j]; pz[u] = g[64 + j]; pn[u] = g[128 + j];
    }
    __syncthreads();

    int p = 0;
    for (int t = 0; t < T_LEN; t += 4) {
#pragma unroll
        for (int u = 0; u < 4; u++) {
            const float igr = pr[u], igz = pz[u], ign = pn[u];
            const int tn = t + 4 + u;
            if (tn < T_LEN) {
                const float* g = igp + (size_t)tn * G3;
                pr[u] = g[j]; pz[u] = g[64 + j]; pn[u] = g[128 + j];
            }

            ull ar0 = 0, ar1 = 0, az0 = 0, az1 = 0, an0 = 0, an1 = 0;
            const float* hb = sh_h[p];
#pragma unroll
            for (int q = 0; q < 32; q += 2) {
                ulonglong2 h2 = *(const ulonglong2*)&hb[2 * q];
                ffma2(ar0, wr[q], h2.x); ffma2(ar1, wr[q + 1], h2.y);
                ffma2(az0, wz[q], h2.x); ffma2(az1, wz[q + 1], h2.y);
                ffma2(an0, wn[q], h2.x); ffma2(an1, wn[q + 1], h2.y);
            }
            float x0, x1, y0, y1;
            unpack2(x0, x1, ar0); unpack2(y0, y1, ar1);
            const float hgr = (x0 + x1) + (y0 + y1);
            unpack2(x0, x1, az0); unpack2(y0, y1, az1);
            const float hgz = (x0 + x1) + (y0 + y1);
            unpack2(x0, x1, an0); unpack2(y0, y1, an1);
            const float hgn = (x0 + x1) + (y0 + y1);

            const float r = fsigmoid(igr + hgr);
            const float z = fsigmoid(igz + hgz);
            const float n = ftanh(ign + r * (hgn + bn));
            hreg = n + z * (hreg - n);

            sh_h[1 - p][j] = hreg;
            __syncthreads();
            p ^= 1;
        }
    }

    sh_h[0][j] = hreg;
    __syncthreads();
    if (j < 2) {
        float acc = 0.f;
#pragma unroll 8
        for (int k = 0; k < 64; k++) acc += wout[j * 64 + k] * sh_h[0][k];
        out[b * 2 + j] = fsigmoid(acc + out_bias[j]);
    }
}

// ---------------------------------------------------------------------------
extern "C" void kernel_launch(void* const* d_in, const int* in_sizes, int n_in,
                              void* d_out, int out_size)
{
    const float* x        = (const float*)d_in[0];
    const float* wih      = (const float*)d_in[1];
    const float* whh      = (const float*)d_in[2];
    const float* bias     = (const float*)d_in[3];
    const float* bias_n   = (const float*)d_in[4];
    const float* wout     = (const float*)d_in[5];
    const float* out_bias = (const float*)d_in[6];
    float* out = (float*)d_out;

    cudaFuncSetAttribute(ig_mma, cudaFuncAttributeMaxDynamicSharedMemorySize, SM_TOT);

    prep_b<<<(NCHUNK * G3 * KC + 255) / 256, 256>>>(wih, bias);
    ig_mma<<<(B_SZ * T_LEN) / M_TILE, 256, SM_TOT>>>(x);
    gru_scan<<<B_SZ, 64>>>(whh, bias_n, wout, out_bias, out);
}